// round 4
// baseline (speedup 1.0000x reference)
#include <cuda_runtime.h>
#include <math.h>

// Problem constants
#define B_  16
#define T_  32
#define C_  64
#define H_  32
#define W_  32
#define CHW   (C_ * H_ * W_)       // 65536
#define CHW4  (CHW / 4)            // 16384 float4 per (b,t) slice
#define NTHREADS_TOTAL (B_ * CHW4 / 2)   // 131072 threads, 2 chains each

#define VTH_M   0.5f
#define VTH_S   0.1f
#define DECAY_M 2.0f
#define DECAY_S 0.1f

#define PF 4   // prefetch ring depth

__device__ __forceinline__ float softplus_acc(float z) {
    if (z > 20.0f) return z;
    return log1pf(expf(z));
}

__device__ __forceinline__ float sigmoid_acc(float z) {
    return 1.0f / (1.0f + expf(-z));
}

__global__ void __launch_bounds__(128, 7) hlif_kernel(
    const float4* __restrict__ x,
    const float*  __restrict__ vth_raw,
    const float*  __restrict__ decay_raw,
    float4*       __restrict__ out)
{
    int tid = blockIdx.x * blockDim.x + threadIdx.x;   // 0 .. 131071
    int p  = tid & (CHW4 - 1);      // vec index within (C,H,W)
    int b0 = tid >> 14;             // 0..7 ; second chain is b0+8

    // chain base pointers (float4 units)
    const size_t cstride = (size_t)T_ * CHW4;          // per-batch stride
    const float4* xb = x   + (size_t)b0 * cstride + p;
    float4*       ob = out + (size_t)b0 * cstride + p;
    const size_t boff = (size_t)8 * cstride;           // offset to chain 2 (b0+8)

    // Kick off prefetch pipeline first so param MUFU math overlaps DRAM.
    float4 buf[PF];
    #pragma unroll
    for (int i = 0; i < PF; ++i)
        buf[i] = __ldcs(xb + (size_t)i * CHW4);

    // per-neuron params (4 neurons per thread; shared by both chains)
    float4 vr = reinterpret_cast<const float4*>(vth_raw)[p];
    float4 dr = reinterpret_cast<const float4*>(decay_raw)[p];

    float4 vth, dec;
    vth.x = softplus_acc(fmaf(vr.x, VTH_S, VTH_M)) + 0.01f;
    vth.y = softplus_acc(fmaf(vr.y, VTH_S, VTH_M)) + 0.01f;
    vth.z = softplus_acc(fmaf(vr.z, VTH_S, VTH_M)) + 0.01f;
    vth.w = softplus_acc(fmaf(vr.w, VTH_S, VTH_M)) + 0.01f;
    dec.x = fminf(fmaxf(sigmoid_acc(fmaf(dr.x, DECAY_S, DECAY_M)), 0.0f), 0.99f);
    dec.y = fminf(fmaxf(sigmoid_acc(fmaf(dr.y, DECAY_S, DECAY_M)), 0.0f), 0.99f);
    dec.z = fminf(fmaxf(sigmoid_acc(fmaf(dr.z, DECAY_S, DECAY_M)), 0.0f), 0.99f);
    dec.w = fminf(fmaxf(sigmoid_acc(fmaf(dr.w, DECAY_S, DECAY_M)), 0.0f), 0.99f);

    float4 v = make_float4(0.0f, 0.0f, 0.0f, 0.0f);

    // Fused 2-chain loop: steps 0..31 = chain b0, steps 32..63 = chain b0+8.
    // The PF ring spans the chain boundary, so chain 2's first loads are in
    // flight while chain 1 finishes. All selects below fold at compile time.
    #pragma unroll
    for (int s = 0; s < 2 * T_; ++s) {
        if (s == T_) v = make_float4(0.0f, 0.0f, 0.0f, 0.0f);  // reset for chain 2

        float4 xt = buf[s & (PF - 1)];

        int sp = s + PF;
        if (sp < 2 * T_) {
            size_t off = (sp < T_) ? ((size_t)sp * CHW4)
                                   : (boff + (size_t)(sp - T_) * CHW4);
            buf[s & (PF - 1)] = __ldcs(xb + off);
        }

        float4 sv;
        v.x = fmaf(v.x, dec.x, xt.x);
        v.y = fmaf(v.y, dec.y, xt.y);
        v.z = fmaf(v.z, dec.z, xt.z);
        v.w = fmaf(v.w, dec.w, xt.w);

        sv.x = (v.x - vth.x > 0.0f) ? 1.0f : 0.0f;
        sv.y = (v.y - vth.y > 0.0f) ? 1.0f : 0.0f;
        sv.z = (v.z - vth.z > 0.0f) ? 1.0f : 0.0f;
        sv.w = (v.w - vth.w > 0.0f) ? 1.0f : 0.0f;

        v.x -= sv.x * vth.x;
        v.y -= sv.y * vth.y;
        v.z -= sv.z * vth.z;
        v.w -= sv.w * vth.w;

        size_t oo = (s < T_) ? ((size_t)s * CHW4)
                             : (boff + (size_t)(s - T_) * CHW4);
        __stcs(ob + oo, sv);
    }
}

extern "C" void kernel_launch(void* const* d_in, const int* in_sizes, int n_in,
                              void* d_out, int out_size)
{
    const float4* x         = (const float4*)d_in[0];
    const float*  vth_raw   = (const float*)d_in[1];
    const float*  decay_raw = (const float*)d_in[2];
    float4* out = (float4*)d_out;

    const int threads = 128;
    const int blocks  = NTHREADS_TOTAL / threads;   // 1024 blocks, single wave
    hlif_kernel<<<blocks, threads>>>(x, vth_raw, decay_raw, out);
}

// round 5
// speedup vs baseline: 1.0689x; 1.0689x over previous
#include <cuda_runtime.h>
#include <math.h>

// Problem constants
#define B_  16
#define T_  32
#define C_  64
#define H_  32
#define W_  32
#define CHW   (C_ * H_ * W_)       // 65536
#define CHW4  (CHW / 4)            // 16384 float4 per (b,t) slice
#define NVEC  (B_ * CHW4)          // 262144 threads, one chain each

#define VTH_M   0.5f
#define VTH_S   0.1f
#define DECAY_M 2.0f
#define DECAY_S 0.1f

#define SEG 8                      // t-steps per read-burst/write-burst segment
#define NSEG (T_ / SEG)            // 4 segments

__device__ __forceinline__ float softplus_acc(float z) {
    if (z > 20.0f) return z;
    return log1pf(expf(z));
}

__device__ __forceinline__ float sigmoid_acc(float z) {
    return 1.0f / (1.0f + expf(-z));
}

__global__ void __launch_bounds__(256) hlif_kernel(
    const float4* __restrict__ x,
    const float*  __restrict__ vth_raw,
    const float*  __restrict__ decay_raw,
    float4*       __restrict__ out)
{
    int idx = blockIdx.x * blockDim.x + threadIdx.x;   // 0 .. NVEC-1
    int p = idx & (CHW4 - 1);       // vec index within (C,H,W)
    int b = idx >> 14;              // batch index (CHW4 = 2^14)

    const float4* xb = x   + (size_t)b * (T_ * CHW4) + p;
    float4*       ob = out + (size_t)b * (T_ * CHW4) + p;

    // First read burst overlaps the MUFU-heavy param math.
    float4 buf[SEG];
    #pragma unroll
    for (int i = 0; i < SEG; ++i)
        buf[i] = __ldcs(xb + (size_t)i * CHW4);

    // per-neuron params (4 neurons per thread)
    float4 vr = reinterpret_cast<const float4*>(vth_raw)[p];
    float4 dr = reinterpret_cast<const float4*>(decay_raw)[p];

    float4 vth, dec;
    vth.x = softplus_acc(fmaf(vr.x, VTH_S, VTH_M)) + 0.01f;
    vth.y = softplus_acc(fmaf(vr.y, VTH_S, VTH_M)) + 0.01f;
    vth.z = softplus_acc(fmaf(vr.z, VTH_S, VTH_M)) + 0.01f;
    vth.w = softplus_acc(fmaf(vr.w, VTH_S, VTH_M)) + 0.01f;
    dec.x = fminf(fmaxf(sigmoid_acc(fmaf(dr.x, DECAY_S, DECAY_M)), 0.0f), 0.99f);
    dec.y = fminf(fmaxf(sigmoid_acc(fmaf(dr.y, DECAY_S, DECAY_M)), 0.0f), 0.99f);
    dec.z = fminf(fmaxf(sigmoid_acc(fmaf(dr.z, DECAY_S, DECAY_M)), 0.0f), 0.99f);
    dec.w = fminf(fmaxf(sigmoid_acc(fmaf(dr.w, DECAY_S, DECAY_M)), 0.0f), 0.99f);

    float4 v = make_float4(0.0f, 0.0f, 0.0f, 0.0f);

    #pragma unroll
    for (int seg = 0; seg < NSEG; ++seg) {
        const int t0 = seg * SEG;

        // Compute 8 steps; overwrite the ring slot with the spike (in-place,
        // no extra registers) so reads and writes form separate bursts.
        #pragma unroll
        for (int i = 0; i < SEG; ++i) {
            float4 xt = buf[i];
            float4 s;
            v.x = fmaf(v.x, dec.x, xt.x);
            v.y = fmaf(v.y, dec.y, xt.y);
            v.z = fmaf(v.z, dec.z, xt.z);
            v.w = fmaf(v.w, dec.w, xt.w);

            s.x = (v.x - vth.x > 0.0f) ? 1.0f : 0.0f;
            s.y = (v.y - vth.y > 0.0f) ? 1.0f : 0.0f;
            s.z = (v.z - vth.z > 0.0f) ? 1.0f : 0.0f;
            s.w = (v.w - vth.w > 0.0f) ? 1.0f : 0.0f;

            v.x -= s.x * vth.x;
            v.y -= s.y * vth.y;
            v.z -= s.z * vth.z;
            v.w -= s.w * vth.w;

            buf[i] = s;
        }

        // Write burst: 8 consecutive STG.128 (fire-and-forget).
        #pragma unroll
        for (int i = 0; i < SEG; ++i)
            __stcs(ob + (size_t)(t0 + i) * CHW4, buf[i]);

        // Read burst for next segment: 8 consecutive LDG.128.
        if (seg + 1 < NSEG) {
            #pragma unroll
            for (int i = 0; i < SEG; ++i)
                buf[i] = __ldcs(xb + (size_t)(t0 + SEG + i) * CHW4);
        }
    }
}

extern "C" void kernel_launch(void* const* d_in, const int* in_sizes, int n_in,
                              void* d_out, int out_size)
{
    const float4* x         = (const float4*)d_in[0];
    const float*  vth_raw   = (const float*)d_in[1];
    const float*  decay_raw = (const float*)d_in[2];
    float4* out = (float4*)d_out;

    const int threads = 256;
    const int blocks  = NVEC / threads;   // 1024
    hlif_kernel<<<blocks, threads>>>(x, vth_raw, decay_raw, out);
}